// round 1
// baseline (speedup 1.0000x reference)
#include <cuda_runtime.h>
#include <math.h>

#define Bn   64
#define Sn   512
#define INn  1024
#define HIDn 1024
#define G4   4096
#define Mtot 32768   // Bn*Sn

// Scratch: G = x@U + bias, [Mtot, 4H] fp32 (512 MB), plus LSTM state buffers.
__device__ float g_scr[(size_t)Mtot * G4];
__device__ float h_ping[Bn * HIDn];
__device__ float h_pong[Bn * HIDn];
__device__ float c_buf[Bn * HIDn];

__global__ void init_state_k(const float* __restrict__ h0,
                             const float* __restrict__ c0) {
    int i = blockIdx.x * blockDim.x + threadIdx.x;
    if (i < Bn * HIDn) {
        h_ping[i] = h0[i];
        c_buf[i]  = c0[i];
    }
}

// ---------------------------------------------------------------------------
// Phase 1: G[m][n] = sum_k x[m][k] * U[k][n] + bias[n]
// 128x128 block tile, KT=16, 256 threads, 8x8 micro-tile (AI=4 FMA/float).
// ---------------------------------------------------------------------------
__global__ __launch_bounds__(256) void gemm_xu_k(const float* __restrict__ x,
                                                 const float* __restrict__ U,
                                                 const float* __restrict__ bias) {
    __shared__ float As[16][128];   // [k][m]
    __shared__ float Bs[16][128];   // [k][n]

    const int m0  = blockIdx.y * 128;
    const int n0  = blockIdx.x * 128;
    const int tid = threadIdx.x;
    const int tm  = (tid >> 4) * 8;   // 0..120
    const int tn  = (tid & 15) * 8;   // 0..120

    float acc[8][8];
#pragma unroll
    for (int i = 0; i < 8; ++i)
#pragma unroll
        for (int j = 0; j < 8; ++j) acc[i][j] = 0.0f;

    for (int k0 = 0; k0 < INn; k0 += 16) {
        // Load A tile (x): 128 rows x 16 k, float4 along k, store transposed.
#pragma unroll
        for (int i = 0; i < 2; ++i) {
            int e   = tid + i * 256;       // 0..511 float4 slots
            int row = e >> 2;              // 0..127
            int kq  = (e & 3) << 2;        // 0,4,8,12
            float4 v = *(const float4*)(x + (size_t)(m0 + row) * INn + k0 + kq);
            As[kq + 0][row] = v.x;
            As[kq + 1][row] = v.y;
            As[kq + 2][row] = v.z;
            As[kq + 3][row] = v.w;
        }
        // Load B tile (U): 16 k x 128 n, float4 along n (fully coalesced).
#pragma unroll
        for (int i = 0; i < 2; ++i) {
            int e  = tid + i * 256;        // 0..511 float4 slots
            int kr = e >> 5;               // 0..15
            int nq = (e & 31) << 2;        // 0..124
            float4 v = *(const float4*)(U + (size_t)(k0 + kr) * G4 + n0 + nq);
            *(float4*)&Bs[kr][nq] = v;
        }
        __syncthreads();

#pragma unroll
        for (int kk = 0; kk < 16; ++kk) {
            float a[8], b[8];
            *(float4*)&a[0] = *(const float4*)&As[kk][tm];
            *(float4*)&a[4] = *(const float4*)&As[kk][tm + 4];
            *(float4*)&b[0] = *(const float4*)&Bs[kk][tn];
            *(float4*)&b[4] = *(const float4*)&Bs[kk][tn + 4];
#pragma unroll
            for (int i = 0; i < 8; ++i)
#pragma unroll
                for (int j = 0; j < 8; ++j) acc[i][j] += a[i] * b[j];
        }
        __syncthreads();
    }

    // Epilogue: add bias, store to g_scr.
#pragma unroll
    for (int i = 0; i < 8; ++i) {
        size_t row = (size_t)(m0 + tm + i) * G4;
#pragma unroll
        for (int jq = 0; jq < 8; jq += 4) {
            float4 w;
            w.x = acc[i][jq + 0] + bias[n0 + tn + jq + 0];
            w.y = acc[i][jq + 1] + bias[n0 + tn + jq + 1];
            w.z = acc[i][jq + 2] + bias[n0 + tn + jq + 2];
            w.w = acc[i][jq + 3] + bias[n0 + tn + jq + 3];
            *(float4*)(g_scr + row + n0 + tn + jq) = w;
        }
    }
}

// ---------------------------------------------------------------------------
// Phase 2: one kernel per timestep.
// Block owns 8 h-columns j0..j0+7 -> computes the 4 gate columns for each
// (32 GEMM output cols), 64 batch rows. 128 threads, 4x4 micro-tile.
// Gates applied in-block via smem staging; h ping-pongs across steps.
// ---------------------------------------------------------------------------
__global__ __launch_bounds__(128) void lstm_step_k(const float* __restrict__ Vm,
                                                   float* __restrict__ out,
                                                   int t) {
    const float* hin  = (t & 1) ? h_pong : h_ping;
    float*       hout = (t & 1) ? h_ping : h_pong;

    const int j0  = blockIdx.x * 8;
    const int tid = threadIdx.x;
    const int tr  = (tid >> 3) * 4;   // row group: 0..60
    const int tc  = (tid & 7) * 4;    // col group: 0..28 (of 32 gate cols)

    __shared__ float hs[16][64];      // [k][m]
    __shared__ float vs[16][32];      // [k][c]  c = gate*8 + jj
    __shared__ float gsm[64][33];     // staged pre-activations (padded)

    float acc[4][4];
#pragma unroll
    for (int i = 0; i < 4; ++i)
#pragma unroll
        for (int j = 0; j < 4; ++j) acc[i][j] = 0.0f;

    for (int k0 = 0; k0 < HIDn; k0 += 16) {
        // h tile: 64 rows x 16 k  (256 float4, 2 per thread)
#pragma unroll
        for (int i = 0; i < 2; ++i) {
            int e  = tid + i * 128;
            int m  = e >> 2;           // 0..63
            int kq = (e & 3) << 2;     // 0,4,8,12
            float4 v = *(const float4*)(hin + (size_t)m * HIDn + k0 + kq);
            hs[kq + 0][m] = v.x;
            hs[kq + 1][m] = v.y;
            hs[kq + 2][m] = v.z;
            hs[kq + 3][m] = v.w;
        }
        // V tile: 16 k x 32 cols (gate-strided), 1 float4 per thread
        {
            int e  = tid;              // 0..127 float4 slots
            int k  = e >> 3;           // 0..15
            int cq = (e & 7) << 2;     // 0,4,...,28 (stays within one gate group of 8)
            int col = (cq >> 3) * HIDn + j0 + (cq & 7);
            float4 v = *(const float4*)(Vm + (size_t)(k0 + k) * G4 + col);
            *(float4*)&vs[k][cq] = v;
        }
        __syncthreads();

#pragma unroll
        for (int kk = 0; kk < 16; ++kk) {
            float a[4], b[4];
            *(float4*)&a[0] = *(const float4*)&hs[kk][tr];
            *(float4*)&b[0] = *(const float4*)&vs[kk][tc];
#pragma unroll
            for (int i = 0; i < 4; ++i)
#pragma unroll
                for (int j = 0; j < 4; ++j) acc[i][j] += a[i] * b[j];
        }
        __syncthreads();
    }

    // Add precomputed x@U + bias, stage full 64x32 gate tile in smem.
#pragma unroll
    for (int i = 0; i < 4; ++i) {
        int m = tr + i;
        size_t grow = ((size_t)(m * Sn + t)) * G4;
#pragma unroll
        for (int j = 0; j < 4; ++j) {
            int c   = tc + j;
            int col = (c >> 3) * HIDn + j0 + (c & 7);
            gsm[m][c] = acc[i][j] + g_scr[grow + col];
        }
    }
    __syncthreads();

    // Gates: 64 rows x 8 h-cols = 512 cells, 4 per thread.
#pragma unroll
    for (int p = 0; p < 4; ++p) {
        int e  = tid + p * 128;
        int m  = e >> 3;
        int jj = e & 7;
        float gn = gsm[m][jj];
        float gi = gsm[m][8 + jj];
        float gf = gsm[m][16 + jj];
        float go = gsm[m][24 + jj];
        float nv = tanhf(gn);
        float iv = 1.0f / (1.0f + expf(-gi));
        float fv = 1.0f / (1.0f + expf(-gf));
        float ov = 1.0f / (1.0f + expf(-go));
        int col = j0 + jj;
        int idx = m * HIDn + col;
        float cn = c_buf[idx] * fv + nv * iv;
        float hn = tanhf(cn) * ov;
        c_buf[idx] = cn;
        hout[idx]  = hn;
        out[((size_t)m * Sn + t) * HIDn + col] = hn;
    }
}

__global__ void finalize_k(float* __restrict__ out_tail) {
    int i = blockIdx.x * blockDim.x + threadIdx.x;
    if (i < Bn * HIDn) {
        // 512 steps: final h lands in h_ping (last step t=511 writes ping).
        out_tail[i]             = h_ping[i];
        out_tail[Bn * HIDn + i] = c_buf[i];
    }
}

extern "C" void kernel_launch(void* const* d_in, const int* in_sizes, int n_in,
                              void* d_out, int out_size) {
    const float* x    = (const float*)d_in[0];
    const float* U    = (const float*)d_in[1];
    const float* V    = (const float*)d_in[2];
    const float* bias = (const float*)d_in[3];
    const float* h0   = (const float*)d_in[4];
    const float* c0   = (const float*)d_in[5];
    float* out = (float*)d_out;

    init_state_k<<<(Bn * HIDn + 255) / 256, 256>>>(h0, c0);

    dim3 gg(G4 / 128, Mtot / 128);
    gemm_xu_k<<<gg, 256>>>(x, U, bias);

    for (int t = 0; t < Sn; ++t) {
        lstm_step_k<<<HIDn / 8, 128>>>(V, out, t);
    }

    // Append (h_fin, c_fin) if the harness expects them.
    long long main_elems = (long long)Bn * Sn * HIDn;
    if ((long long)out_size >= main_elems + 2LL * Bn * HIDn) {
        finalize_k<<<(Bn * HIDn + 255) / 256, 256>>>(out + main_elems);
    }
}

// round 2
// speedup vs baseline: 1.3708x; 1.3708x over previous
#include <cuda_runtime.h>
#include <math.h>

#define Bn   64
#define Sn   512
#define INn  1024
#define HIDn 1024
#define G4   4096
#define Mtot 32768   // Bn*Sn
#define NCTA 128
#define NTHR 256
#define KC   32      // k-chunk for h streaming
#define HSP  66      // padded row for hs (bank-conflict-free transpose)
#define GSP  34      // padded row for gate staging

// Scratch: G = x@U + bias, [Mtot, 4H] fp32 (512 MB), plus LSTM state buffers.
__device__ float g_scr[(size_t)Mtot * G4];
__device__ float h_ping[Bn * HIDn];
__device__ float h_pong[Bn * HIDn];
__device__ float c_buf[Bn * HIDn];
__device__ unsigned int g_count;

__global__ void init_state_k(const float* __restrict__ h0,
                             const float* __restrict__ c0) {
    int i = blockIdx.x * blockDim.x + threadIdx.x;
    if (i < Bn * HIDn) {
        h_ping[i] = h0[i];
        c_buf[i]  = c0[i];
    }
    if (i == 0) g_count = 0u;
}

// ---------------------------------------------------------------------------
// Phase 1: G[m][n] = sum_k x[m][k] * U[k][n] + bias[n]
// 128x128 block tile, KT=16, 256 threads, 8x8 micro-tile.
// ---------------------------------------------------------------------------
__global__ __launch_bounds__(256) void gemm_xu_k(const float* __restrict__ x,
                                                 const float* __restrict__ U,
                                                 const float* __restrict__ bias) {
    __shared__ float As[16][128];   // [k][m]
    __shared__ float Bs[16][128];   // [k][n]

    const int m0  = blockIdx.y * 128;
    const int n0  = blockIdx.x * 128;
    const int tid = threadIdx.x;
    const int tm  = (tid >> 4) * 8;
    const int tn  = (tid & 15) * 8;

    float acc[8][8];
#pragma unroll
    for (int i = 0; i < 8; ++i)
#pragma unroll
        for (int j = 0; j < 8; ++j) acc[i][j] = 0.0f;

    for (int k0 = 0; k0 < INn; k0 += 16) {
#pragma unroll
        for (int i = 0; i < 2; ++i) {
            int e   = tid + i * 256;
            int row = e >> 2;
            int kq  = (e & 3) << 2;
            float4 v = *(const float4*)(x + (size_t)(m0 + row) * INn + k0 + kq);
            As[kq + 0][row] = v.x;
            As[kq + 1][row] = v.y;
            As[kq + 2][row] = v.z;
            As[kq + 3][row] = v.w;
        }
#pragma unroll
        for (int i = 0; i < 2; ++i) {
            int e  = tid + i * 256;
            int kr = e >> 5;
            int nq = (e & 31) << 2;
            float4 v = *(const float4*)(U + (size_t)(k0 + kr) * G4 + n0 + nq);
            *(float4*)&Bs[kr][nq] = v;
        }
        __syncthreads();

#pragma unroll
        for (int kk = 0; kk < 16; ++kk) {
            float a[8], b[8];
            *(float4*)&a[0] = *(const float4*)&As[kk][tm];
            *(float4*)&a[4] = *(const float4*)&As[kk][tm + 4];
            *(float4*)&b[0] = *(const float4*)&Bs[kk][tn];
            *(float4*)&b[4] = *(const float4*)&Bs[kk][tn + 4];
#pragma unroll
            for (int i = 0; i < 8; ++i)
#pragma unroll
                for (int j = 0; j < 8; ++j) acc[i][j] += a[i] * b[j];
        }
        __syncthreads();
    }

#pragma unroll
    for (int i = 0; i < 8; ++i) {
        size_t row = (size_t)(m0 + tm + i) * G4;
#pragma unroll
        for (int jq = 0; jq < 8; jq += 4) {
            float4 w;
            w.x = acc[i][jq + 0] + bias[n0 + tn + jq + 0];
            w.y = acc[i][jq + 1] + bias[n0 + tn + jq + 1];
            w.z = acc[i][jq + 2] + bias[n0 + tn + jq + 2];
            w.w = acc[i][jq + 3] + bias[n0 + tn + jq + 3];
            *(float4*)(g_scr + row + n0 + tn + jq) = w;
        }
    }
}

// ---------------------------------------------------------------------------
// Phase 2: PERSISTENT recurrence kernel. 128 co-resident CTAs, each owns 8
// h-columns (-> 32 gate columns). V slice [1024x32] lives in SMEM for all
// 512 steps. Grid-wide barrier (monotone counter) between steps.
// ---------------------------------------------------------------------------
__device__ __forceinline__ float sigmoid_f(float x) {
    return 1.0f / (1.0f + __expf(-x));
}
__device__ __forceinline__ float tanh_f(float x) {
    return 2.0f / (1.0f + __expf(-2.0f * x)) - 1.0f;
}

__global__ __launch_bounds__(NTHR, 1) void lstm_persist_k(const float* __restrict__ Vm,
                                                          float* __restrict__ out) {
    extern __shared__ float smem[];
    float* vs  = smem;                       // [1024][32]
    float* hsb = vs + 1024 * 32;             // [2][KC][HSP]
    float* gsm = hsb + 2 * KC * HSP;         // [64][GSP]

    const int tid = threadIdx.x;
    const int j0  = blockIdx.x * 8;

    // Load V slice once: cols {g*1024 + j0 .. j0+7} for g in 0..3, all 1024 k.
    for (int e = tid; e < 1024 * 8; e += NTHR) {
        int k = e >> 3;
        int q = e & 7;
        int gq = q >> 1;
        int half = q & 1;
        float4 v = *(const float4*)(Vm + (size_t)k * G4 + gq * HIDn + j0 + half * 4);
        *(float4*)&vs[k * 32 + gq * 8 + half * 4] = v;
    }
    __syncthreads();

    const int tr = (tid >> 3) * 2;   // 0..62 (2 rows)
    const int tc = (tid & 7) * 4;    // 0..28 (4 cols, within one gate group)

    // Indices for h chunk loading (2 float4 per thread per chunk).
    const int e0 = tid,       m0_ = e0 >> 3, kq0 = (e0 & 7) * 4;
    const int e1 = tid + 256, m1_ = e1 >> 3, kq1 = (e1 & 7) * 4;

    for (int t = 0; t < Sn; ++t) {
        const float* hin  = (t & 1) ? h_pong : h_ping;
        float*       hout = (t & 1) ? h_ping : h_pong;

        float acc[2][4];
#pragma unroll
        for (int i = 0; i < 2; ++i)
#pragma unroll
            for (int j = 0; j < 4; ++j) acc[i][j] = 0.0f;

        // Prefetch chunk 0
        float4 pf0 = *(const float4*)(hin + (size_t)m0_ * HIDn + kq0);
        float4 pf1 = *(const float4*)(hin + (size_t)m1_ * HIDn + kq1);

        for (int kc = 0; kc < HIDn / KC; ++kc) {
            float* hb = hsb + (kc & 1) * (KC * HSP);
            // Store prefetched chunk (transposed)
            hb[(kq0 + 0) * HSP + m0_] = pf0.x;
            hb[(kq0 + 1) * HSP + m0_] = pf0.y;
            hb[(kq0 + 2) * HSP + m0_] = pf0.z;
            hb[(kq0 + 3) * HSP + m0_] = pf0.w;
            hb[(kq1 + 0) * HSP + m1_] = pf1.x;
            hb[(kq1 + 1) * HSP + m1_] = pf1.y;
            hb[(kq1 + 2) * HSP + m1_] = pf1.z;
            hb[(kq1 + 3) * HSP + m1_] = pf1.w;
            __syncthreads();

            // Prefetch next chunk (overlaps compute)
            if (kc + 1 < HIDn / KC) {
                int kb = (kc + 1) * KC;
                pf0 = *(const float4*)(hin + (size_t)m0_ * HIDn + kb + kq0);
                pf1 = *(const float4*)(hin + (size_t)m1_ * HIDn + kb + kq1);
            }

            const float* vrow = vs + kc * (KC * 32);
#pragma unroll
            for (int kk = 0; kk < KC; ++kk) {
                float2 a = *(const float2*)&hb[kk * HSP + tr];
                float4 b = *(const float4*)&vrow[kk * 32 + tc];
                acc[0][0] += a.x * b.x;
                acc[0][1] += a.x * b.y;
                acc[0][2] += a.x * b.z;
                acc[0][3] += a.x * b.w;
                acc[1][0] += a.y * b.x;
                acc[1][1] += a.y * b.y;
                acc[1][2] += a.y * b.z;
                acc[1][3] += a.y * b.w;
            }
        }

        // Epilogue: add x@U+bias, stage to smem.
#pragma unroll
        for (int i = 0; i < 2; ++i) {
            int m = tr + i;
            const float* gp = g_scr + ((size_t)(m * Sn + t)) * G4
                              + (tc >> 3) * HIDn + j0 + (tc & 7);
            float4 gv = *(const float4*)gp;
            gsm[m * GSP + tc + 0] = acc[i][0] + gv.x;
            gsm[m * GSP + tc + 1] = acc[i][1] + gv.y;
            gsm[m * GSP + tc + 2] = acc[i][2] + gv.z;
            gsm[m * GSP + tc + 3] = acc[i][3] + gv.w;
        }
        __syncthreads();

        // Gates: 64 rows x 8 h-cols = 512 cells, 2 per thread.
#pragma unroll
        for (int p = 0; p < 2; ++p) {
            int e  = tid + p * 256;
            int m  = e >> 3;
            int jj = e & 7;
            float gn = gsm[m * GSP + jj];
            float gi = gsm[m * GSP + 8 + jj];
            float gf = gsm[m * GSP + 16 + jj];
            float go = gsm[m * GSP + 24 + jj];
            float nv = tanh_f(gn);
            float iv = sigmoid_f(gi);
            float fv = sigmoid_f(gf);
            float ov = sigmoid_f(go);
            int idx = m * HIDn + j0 + jj;
            float cn = c_buf[idx] * fv + nv * iv;
            c_buf[idx] = cn;
            float hn = tanh_f(cn) * ov;
            hout[idx] = hn;
            out[((size_t)m * Sn + t) * HIDn + j0 + jj] = hn;
        }

        // ---- grid-wide barrier ----
        __threadfence();
        __syncthreads();
        if (tid == 0) {
            atomicAdd(&g_count, 1u);
            unsigned target = (unsigned)(t + 1) * NCTA;
            volatile unsigned* vc = &g_count;
            int spins = 0;
            while (*vc < target) {
                if (++spins > 64) { __nanosleep(128); spins = 0; }
            }
        }
        __syncthreads();
        __threadfence();
    }
}

__global__ void finalize_k(float* __restrict__ out_tail) {
    int i = blockIdx.x * blockDim.x + threadIdx.x;
    if (i < Bn * HIDn) {
        // 512 steps: final h lands in h_ping (last step t=511 writes ping).
        out_tail[i]             = h_ping[i];
        out_tail[Bn * HIDn + i] = c_buf[i];
    }
}

extern "C" void kernel_launch(void* const* d_in, const int* in_sizes, int n_in,
                              void* d_out, int out_size) {
    const float* x    = (const float*)d_in[0];
    const float* U    = (const float*)d_in[1];
    const float* V    = (const float*)d_in[2];
    const float* bias = (const float*)d_in[3];
    const float* h0   = (const float*)d_in[4];
    const float* c0   = (const float*)d_in[5];
    float* out = (float*)d_out;

    const int smem_bytes = (1024 * 32 + 2 * KC * HSP + 64 * GSP) * sizeof(float);
    cudaFuncSetAttribute(lstm_persist_k,
                         cudaFuncAttributeMaxDynamicSharedMemorySize, smem_bytes);

    init_state_k<<<(Bn * HIDn + 255) / 256, 256>>>(h0, c0);

    dim3 gg(G4 / 128, Mtot / 128);
    gemm_xu_k<<<gg, 256>>>(x, U, bias);

    lstm_persist_k<<<NCTA, NTHR, smem_bytes>>>(V, out);

    long long main_elems = (long long)Bn * Sn * HIDn;
    if ((long long)out_size >= main_elems + 2LL * Bn * HIDn) {
        finalize_k<<<(Bn * HIDn + 255) / 256, 256>>>(out + main_elems);
    }
}

// round 4
// speedup vs baseline: 3.0807x; 2.2473x over previous
#include <cuda_runtime.h>
#include <cuda_bf16.h>
#include <stdint.h>

#define Bn   64
#define Sn   512
#define INn  1024
#define HIDn 1024
#define G4   4096
#define Mtot 32768
#define NCTA 128
#define NTHR 256

// ---- device scratch ----
__device__ float g_scr[(size_t)Mtot * G4];              // x@U + bias (512MB)
__device__ float c_buf[Bn * HIDn];
__device__ unsigned int g_count;
__device__ __nv_bfloat16 x_hi[(size_t)Mtot * INn];
__device__ __nv_bfloat16 x_lo[(size_t)Mtot * INn];
__device__ __nv_bfloat16 u_hi[(size_t)G4 * INn];        // U^T [N][K]
__device__ __nv_bfloat16 u_lo[(size_t)G4 * INn];
__device__ __nv_bfloat16 vt_hi[(size_t)G4 * HIDn];      // V^T [N][K]
__device__ __nv_bfloat16 vt_lo[(size_t)G4 * HIDn];
__device__ __nv_bfloat16 hb_hi[2][Bn * HIDn];
__device__ __nv_bfloat16 hb_lo[2][Bn * HIDn];

// ---- helpers ----
__device__ __forceinline__ uint32_t smem_u32(const void* p) {
    uint32_t a;
    asm("{ .reg .u64 t; cvta.to.shared.u64 t, %1; cvt.u32.u64 %0, t; }" : "=r"(a) : "l"(p));
    return a;
}
__device__ __forceinline__ void ldsm4(uint32_t r[4], uint32_t addr) {
    asm volatile("ldmatrix.sync.aligned.m8n8.x4.shared.b16 {%0,%1,%2,%3}, [%4];"
        : "=r"(r[0]), "=r"(r[1]), "=r"(r[2]), "=r"(r[3]) : "r"(addr));
}
__device__ __forceinline__ void mma_bf16(float c[4], const uint32_t a[4],
                                         uint32_t b0, uint32_t b1) {
    asm volatile("mma.sync.aligned.m16n8k16.row.col.f32.bf16.bf16.f32 "
        "{%0,%1,%2,%3}, {%4,%5,%6,%7}, {%8,%9}, {%0,%1,%2,%3};"
        : "+f"(c[0]), "+f"(c[1]), "+f"(c[2]), "+f"(c[3])
        : "r"(a[0]), "r"(a[1]), "r"(a[2]), "r"(a[3]), "r"(b0), "r"(b1));
}
__device__ __forceinline__ float sigmoid_f(float x) { return 1.0f / (1.0f + __expf(-x)); }
__device__ __forceinline__ float tanh_f(float x) { return 2.0f / (1.0f + __expf(-2.0f * x)) - 1.0f; }

// ---------------------------------------------------------------------------
__global__ void init_state_k(const float* __restrict__ h0,
                             const float* __restrict__ c0) {
    int i = blockIdx.x * blockDim.x + threadIdx.x;
    if (i < Bn * HIDn) {
        c_buf[i] = c0[i];
        float v = h0[i];
        __nv_bfloat16 h = __float2bfloat16_rn(v);
        hb_hi[0][i] = h;
        hb_lo[0][i] = __float2bfloat16_rn(v - __bfloat162float(h));
    }
    if (i == 0) g_count = 0u;
}

__global__ void conv_x_k(const float* __restrict__ x) {
    size_t i = (size_t)blockIdx.x * blockDim.x + threadIdx.x;
    if (i < (size_t)Mtot * INn) {
        float v = x[i];
        __nv_bfloat16 h = __float2bfloat16_rn(v);
        x_hi[i] = h;
        x_lo[i] = __float2bfloat16_rn(v - __bfloat162float(h));
    }
}
__global__ void conv_u_k(const float* __restrict__ U) {
    size_t i = (size_t)blockIdx.x * blockDim.x + threadIdx.x;
    if (i < (size_t)G4 * INn) {
        size_t n = i / INn, k = i % INn;
        float v = U[k * G4 + n];
        __nv_bfloat16 h = __float2bfloat16_rn(v);
        u_hi[i] = h;
        u_lo[i] = __float2bfloat16_rn(v - __bfloat162float(h));
    }
}
__global__ void conv_v_k(const float* __restrict__ V) {
    size_t i = (size_t)blockIdx.x * blockDim.x + threadIdx.x;
    if (i < (size_t)G4 * HIDn) {
        size_t n = i / HIDn, k = i % HIDn;
        float v = V[k * G4 + n];
        __nv_bfloat16 h = __float2bfloat16_rn(v);
        vt_hi[i] = h;
        vt_lo[i] = __float2bfloat16_rn(v - __bfloat162float(h));
    }
}

// ---------------------------------------------------------------------------
// Phase 1: bf16-split HMMA GEMM.  CTA 128x128, warp 32x64, kc=32, dbl-buffer.
// ---------------------------------------------------------------------------
#define SA   80                 // smem row stride bytes (40 bf16)
#define T1B  (128 * SA)         // 10240 per tile
#define BUFB (4 * T1B)          // Ahi,Alo,Bhi,Blo
#define SM1  (2 * BUFB)         // 81920

#define P1_LOADREG(kc) do { \
    _Pragma("unroll") \
    for (int i = 0; i < 8; ++i) { \
        int e = tid + i * 256; int tl = e >> 9; int rr = (e >> 2) & 127; int c4 = e & 3; \
        const __nv_bfloat16* bp = (tl == 0) ? x_hi : (tl == 1) ? x_lo : (tl == 2) ? u_hi : u_lo; \
        int r0 = ((tl < 2) ? m0 : n0) + rr; \
        pf[i] = *(const float4*)(bp + (size_t)r0 * INn + (kc) * 32 + c4 * 8); \
    } } while (0)
#define P1_STORE(b) do { \
    _Pragma("unroll") \
    for (int i = 0; i < 8; ++i) { \
        int e = tid + i * 256; int tl = e >> 9; int rr = (e >> 2) & 127; int c4 = e & 3; \
        *(float4*)(sm + (b) * BUFB + tl * T1B + rr * SA + c4 * 16) = pf[i]; \
    } } while (0)

__global__ __launch_bounds__(256, 1) void gemm_xu_mma(const float* __restrict__ bias) {
    extern __shared__ char sm[];
    const uint32_t smb = smem_u32(sm);
    const int tid = threadIdx.x, w = tid >> 5, l = tid & 31;
    const int m0 = blockIdx.y * 128, n0 = blockIdx.x * 128;
    const int wm = w >> 1, wn = w & 1;
    const int gr = l >> 2, q = l & 3;
    const int rA = (l & 7) + ((l >> 3) & 1) * 8, cA = (l >> 4) * 16;
    const int rB = (l & 7) + ((l >> 4) & 1) * 8, cB = ((l >> 3) & 1) * 16;

    float acc[2][8][4];
#pragma unroll
    for (int a = 0; a < 2; ++a)
#pragma unroll
        for (int b = 0; b < 8; ++b)
#pragma unroll
            for (int c = 0; c < 4; ++c) acc[a][b][c] = 0.0f;

    float4 pf[8];
    P1_LOADREG(0);
    P1_STORE(0);
    P1_LOADREG(1);
    __syncthreads();

    for (int kc = 0; kc < 32; ++kc) {
        const int buf = kc & 1;
        if (kc + 1 < 32) P1_STORE(buf ^ 1);
        if (kc + 2 < 32) P1_LOADREG(kc + 2);

        const uint32_t base = smb + buf * BUFB;
#pragma unroll
        for (int ks = 0; ks < 2; ++ks) {
            uint32_t ah[2][4], al[2][4];
#pragma unroll
            for (int mfi = 0; mfi < 2; ++mfi) {
                uint32_t ra = base + (uint32_t)((wm * 32 + mfi * 16 + rA) * SA + ks * 32 + cA);
                ldsm4(ah[mfi], ra);
                ldsm4(al[mfi], ra + T1B);
            }
#pragma unroll
            for (int np = 0; np < 4; ++np) {
                uint32_t rb = base + 2 * T1B +
                              (uint32_t)((wn * 64 + np * 16 + rB) * SA + ks * 32 + cB);
                uint32_t bh[4], bl[4];
                ldsm4(bh, rb);
                ldsm4(bl, rb + T1B);
#pragma unroll
                for (int mfi = 0; mfi < 2; ++mfi) {
                    mma_bf16(acc[mfi][2 * np],     ah[mfi], bh[0], bh[1]);
                    mma_bf16(acc[mfi][2 * np + 1], ah[mfi], bh[2], bh[3]);
                    mma_bf16(acc[mfi][2 * np],     al[mfi], bh[0], bh[1]);
                    mma_bf16(acc[mfi][2 * np + 1], al[mfi], bh[2], bh[3]);
                    mma_bf16(acc[mfi][2 * np],     ah[mfi], bl[0], bl[1]);
                    mma_bf16(acc[mfi][2 * np + 1], ah[mfi], bl[2], bl[3]);
                }
            }
        }
        __syncthreads();
    }

    // Epilogue: add bias, write float2 pairs.
#pragma unroll
    for (int mfi = 0; mfi < 2; ++mfi) {
#pragma unroll
        for (int nf = 0; nf < 8; ++nf) {
            int row = m0 + wm * 32 + mfi * 16 + gr;
            int col = n0 + wn * 64 + nf * 8 + 2 * q;
            float2 bz = *(const float2*)(bias + col);
            float2 w0 = make_float2(acc[mfi][nf][0] + bz.x, acc[mfi][nf][1] + bz.y);
            float2 w1 = make_float2(acc[mfi][nf][2] + bz.x, acc[mfi][nf][3] + bz.y);
            *(float2*)(g_scr + (size_t)row * G4 + col) = w0;
            *(float2*)(g_scr + (size_t)(row + 8) * G4 + col) = w1;
        }
    }
}

// ---------------------------------------------------------------------------
// Phase 2: persistent HMMA recurrence. 128 CTAs; V^T slice (hi/lo) resident
// in SMEM; h streamed as bf16 hi/lo chunks; grid barrier between steps.
// ---------------------------------------------------------------------------
#define KP     2064                       // VT smem row stride bytes (1032 bf16)
#define VT_HI  0
#define VT_LO  66048                      // 32*KP
#define HA     132096
#define HTB    17408                      // 64*272 per plane
#define HBUF   34816                      // 2 planes
#define GSM_O  201728                     // HA + 2*HBUF
#define SM2    (GSM_O + 64 * 33 * 4)      // 210176

#define P2_LOADREG(ch) do { \
    _Pragma("unroll") \
    for (int i = 0; i < 8; ++i) { \
        int e = tid + i * 256; int pl = e >> 10; int rr = (e >> 4) & 63; int c16 = e & 15; \
        const __nv_bfloat16* bp = pl ? hl : hh; \
        pf[i] = *(const float4*)(bp + (size_t)rr * HIDn + (ch) * 128 + c16 * 8); \
    } } while (0)
#define P2_STORE(b) do { \
    _Pragma("unroll") \
    for (int i = 0; i < 8; ++i) { \
        int e = tid + i * 256; int pl = e >> 10; int rr = (e >> 4) & 63; int c16 = e & 15; \
        *(float4*)(sm + HA + (b) * HBUF + pl * HTB + rr * 272 + c16 * 16) = pf[i]; \
    } } while (0)

__global__ __launch_bounds__(NTHR, 1) void lstm_persist_mma(float* __restrict__ out) {
    extern __shared__ char sm[];
    const uint32_t smb = smem_u32(sm);
    float* gsm = (float*)(sm + GSM_O);
    const int tid = threadIdx.x, w = tid >> 5, l = tid & 31;
    const int j0 = blockIdx.x * 8;
    const int mf = w >> 1, nb = (w & 1) * 16;
    const int gr = l >> 2, q = l & 3;
    const int rA = (l & 7) + ((l >> 3) & 1) * 8, cA = (l >> 4) * 16;
    const int rB = (l & 7) + ((l >> 4) & 1) * 8, cB = ((l >> 3) & 1) * 16;

    // Load V^T slice (32 rows x 1024 k, hi+lo) once.
#pragma unroll
    for (int i = 0; i < 32; ++i) {
        int e = tid + i * 256;
        int pl = e >> 12, r = (e >> 7) & 31, c = e & 127;
        int gv = (r >> 3) * 1024 + j0 + (r & 7);
        const __nv_bfloat16* src = pl ? vt_lo : vt_hi;
        *(float4*)(sm + (pl ? VT_LO : VT_HI) + r * KP + c * 16) =
            *(const float4*)(src + (size_t)gv * HIDn + c * 8);
    }
    __syncthreads();

    for (int t = 0; t < Sn; ++t) {
        const __nv_bfloat16* hh = hb_hi[t & 1];
        const __nv_bfloat16* hl = hb_lo[t & 1];

        float acc[2][4];
#pragma unroll
        for (int a = 0; a < 2; ++a)
#pragma unroll
            for (int c = 0; c < 4; ++c) acc[a][c] = 0.0f;

        float4 pf[8];
        P2_LOADREG(0);
        P2_STORE(0);
        P2_LOADREG(1);
        __syncthreads();

        for (int ch = 0; ch < 8; ++ch) {
            const int buf = ch & 1;
            if (ch + 1 < 8) P2_STORE(buf ^ 1);
            if (ch + 2 < 8) P2_LOADREG(ch + 2);

            const uint32_t ab = smb + HA + buf * HBUF + (uint32_t)((mf * 16 + rA) * 272 + cA);
            const uint32_t bb = smb + VT_HI + (uint32_t)((nb + rB) * KP + ch * 256 + cB);
#pragma unroll
            for (int ks = 0; ks < 8; ++ks) {
                uint32_t ah[4], al[4], bh[4], bl[4];
                ldsm4(ah, ab + ks * 32);
                ldsm4(al, ab + ks * 32 + HTB);
                ldsm4(bh, bb + ks * 32);
                ldsm4(bl, bb + ks * 32 + VT_LO);
                mma_bf16(acc[0], ah, bh[0], bh[1]);
                mma_bf16(acc[1], ah, bh[2], bh[3]);
                mma_bf16(acc[0], al, bh[0], bh[1]);
                mma_bf16(acc[1], al, bh[2], bh[3]);
                mma_bf16(acc[0], ah, bl[0], bl[1]);
                mma_bf16(acc[1], ah, bl[2], bl[3]);
            }
            __syncthreads();
        }

        // Stage pre-activations (+ precomputed x@U+bias) into gsm.
#pragma unroll
        for (int nf = 0; nf < 2; ++nf) {
            int m = mf * 16 + gr;
            int c = nb + nf * 8 + 2 * q;
            int gcol = (c >> 3) * HIDn + j0 + (c & 7);
            const float* gp = g_scr + ((size_t)(m * Sn + t)) * G4 + gcol;
            float2 g0 = *(const float2*)gp;
            float2 g1 = *(const float2*)(gp + (size_t)8 * Sn * G4);
            gsm[m * 33 + c]           = acc[nf][0] + g0.x;
            gsm[m * 33 + c + 1]       = acc[nf][1] + g0.y;
            gsm[(m + 8) * 33 + c]     = acc[nf][2] + g1.x;
            gsm[(m + 8) * 33 + c + 1] = acc[nf][3] + g1.y;
        }
        __syncthreads();

        // Gates.
        const int nxt = (t & 1) ^ 1;
#pragma unroll
        for (int p = 0; p < 2; ++p) {
            int e  = tid + p * 256;
            int m  = e >> 3;
            int jj = e & 7;
            float gn = gsm[m * 33 + jj];
            float gi = gsm[m * 33 + 8 + jj];
            float gf = gsm[m * 33 + 16 + jj];
            float go = gsm[m * 33 + 24 + jj];
            float nv = tanh_f(gn);
            float iv = sigmoid_f(gi);
            float fv = sigmoid_f(gf);
            float ov = sigmoid_f(go);
            int idx = m * HIDn + j0 + jj;
            float cn = c_buf[idx] * fv + nv * iv;
            c_buf[idx] = cn;
            float hn = tanh_f(cn) * ov;
            out[((size_t)m * Sn + t) * HIDn + j0 + jj] = hn;
            __nv_bfloat16 hb = __float2bfloat16_rn(hn);
            hb_hi[nxt][idx] = hb;
            hb_lo[nxt][idx] = __float2bfloat16_rn(hn - __bfloat162float(hb));
        }

        // ---- grid-wide barrier ----
        __threadfence();
        __syncthreads();
        if (tid == 0) {
            atomicAdd(&g_count, 1u);
            unsigned target = (unsigned)(t + 1) * NCTA;
            volatile unsigned* vc = &g_count;
            int spins = 0;
            while (*vc < target) {
                if (++spins > 64) { __nanosleep(128); spins = 0; }
            }
        }
        __syncthreads();
        __threadfence();
    }
}

__global__ void finalize_k(float* __restrict__ out_tail) {
    int i = blockIdx.x * blockDim.x + threadIdx.x;
    if (i < Bn * HIDn) {
        // after 512 steps the final h lives in hb[0]
        out_tail[i] = __bfloat162float(hb_hi[0][i]) + __bfloat162float(hb_lo[0][i]);
        out_tail[Bn * HIDn + i] = c_buf[i];
    }
}

extern "C" void kernel_launch(void* const* d_in, const int* in_sizes, int n_in,
                              void* d_out, int out_size) {
    const float* x    = (const float*)d_in[0];
    const float* U    = (const float*)d_in[1];
    const float* V    = (const float*)d_in[2];
    const float* bias = (const float*)d_in[3];
    const float* h0   = (const float*)d_in[4];
    const float* c0   = (const float*)d_in[5];
    float* out = (float*)d_out;

    static int attr_done = 0;
    if (!attr_done) {
        cudaFuncSetAttribute(gemm_xu_mma,
                             cudaFuncAttributeMaxDynamicSharedMemorySize, SM1);
        cudaFuncSetAttribute(lstm_persist_mma,
                             cudaFuncAttributeMaxDynamicSharedMemorySize, SM2);
        attr_done = 1;
    }

    init_state_k<<<(Bn * HIDn + 255) / 256, 256>>>(h0, c0);
    conv_x_k<<<(int)(((size_t)Mtot * INn + 255) / 256), 256>>>(x);
    conv_u_k<<<(int)(((size_t)G4 * INn + 255) / 256), 256>>>(U);
    conv_v_k<<<(int)(((size_t)G4 * HIDn + 255) / 256), 256>>>(V);

    dim3 gg(G4 / 128, Mtot / 128);   // x = n-tiles (fast) -> U^T stays L2-hot
    gemm_xu_mma<<<gg, 256, SM1>>>(bias);

    lstm_persist_mma<<<NCTA, NTHR, SM2>>>(out);

    long long main_elems = (long long)Bn * Sn * HIDn;
    if ((long long)out_size >= main_elems + 2LL * Bn * HIDn) {
        finalize_k<<<(Bn * HIDn + 255) / 256, 256>>>(out + main_elems);
    }
}

// round 5
// speedup vs baseline: 4.0818x; 1.3249x over previous
#include <cuda_runtime.h>
#include <cuda_bf16.h>
#include <cuda_fp16.h>
#include <stdint.h>

#define Bn   64
#define Sn   512
#define INn  1024
#define HIDn 1024
#define G4   4096
#define Mtot 32768
#define NCTA 128
#define NTHR 256

// ---- device scratch ----
__device__ float g_scr[(size_t)Mtot * G4];              // x@U + bias (512MB)
__device__ float c_buf[Bn * HIDn];
__device__ float h_fin[Bn * HIDn];
__device__ unsigned int g_count;
__device__ __nv_bfloat16 x_hi[(size_t)Mtot * INn];
__device__ __nv_bfloat16 x_lo[(size_t)Mtot * INn];
__device__ __nv_bfloat16 u_hi[(size_t)G4 * INn];        // U^T [N][K]
__device__ __nv_bfloat16 u_lo[(size_t)G4 * INn];
__device__ __half vt_h[(size_t)G4 * HIDn];              // V^T [N][K] fp16 hi
__device__ __half vt_l[(size_t)G4 * HIDn];              // fp16 lo (subnormal ok)
__device__ __half hb[2][Bn * HIDn];                     // h carried as fp16

// ---- helpers ----
__device__ __forceinline__ uint32_t smem_u32(const void* p) {
    uint32_t a;
    asm("{ .reg .u64 t; cvta.to.shared.u64 t, %1; cvt.u32.u64 %0, t; }" : "=r"(a) : "l"(p));
    return a;
}
__device__ __forceinline__ void ldsm4(uint32_t r[4], uint32_t addr) {
    asm volatile("ldmatrix.sync.aligned.m8n8.x4.shared.b16 {%0,%1,%2,%3}, [%4];"
        : "=r"(r[0]), "=r"(r[1]), "=r"(r[2]), "=r"(r[3]) : "r"(addr));
}
__device__ __forceinline__ void mma_bf16(float c[4], const uint32_t a[4],
                                         uint32_t b0, uint32_t b1) {
    asm volatile("mma.sync.aligned.m16n8k16.row.col.f32.bf16.bf16.f32 "
        "{%0,%1,%2,%3}, {%4,%5,%6,%7}, {%8,%9}, {%0,%1,%2,%3};"
        : "+f"(c[0]), "+f"(c[1]), "+f"(c[2]), "+f"(c[3])
        : "r"(a[0]), "r"(a[1]), "r"(a[2]), "r"(a[3]), "r"(b0), "r"(b1));
}
__device__ __forceinline__ void mma_f16(float c[4], const uint32_t a[4],
                                        uint32_t b0, uint32_t b1) {
    asm volatile("mma.sync.aligned.m16n8k16.row.col.f32.f16.f16.f32 "
        "{%0,%1,%2,%3}, {%4,%5,%6,%7}, {%8,%9}, {%0,%1,%2,%3};"
        : "+f"(c[0]), "+f"(c[1]), "+f"(c[2]), "+f"(c[3])
        : "r"(a[0]), "r"(a[1]), "r"(a[2]), "r"(a[3]), "r"(b0), "r"(b1));
}
__device__ __forceinline__ float sigmoid_f(float x) { return 1.0f / (1.0f + __expf(-x)); }
__device__ __forceinline__ float tanh_f(float x) { return 2.0f / (1.0f + __expf(-2.0f * x)) - 1.0f; }

// ---------------------------------------------------------------------------
__global__ void init_state_k(const float* __restrict__ h0,
                             const float* __restrict__ c0) {
    int i = blockIdx.x * blockDim.x + threadIdx.x;
    if (i < Bn * HIDn) {
        c_buf[i] = c0[i];
        hb[0][i] = __float2half_rn(h0[i]);
        h_fin[i] = h0[i];
    }
    if (i == 0) g_count = 0u;
}

__global__ void conv_x_k(const float* __restrict__ x) {
    size_t i = (size_t)blockIdx.x * blockDim.x + threadIdx.x;
    if (i < (size_t)Mtot * INn) {
        float v = x[i];
        __nv_bfloat16 h = __float2bfloat16_rn(v);
        x_hi[i] = h;
        x_lo[i] = __float2bfloat16_rn(v - __bfloat162float(h));
    }
}
__global__ void conv_u_k(const float* __restrict__ U) {
    size_t i = (size_t)blockIdx.x * blockDim.x + threadIdx.x;
    if (i < (size_t)G4 * INn) {
        size_t n = i / INn, k = i % INn;
        float v = U[k * G4 + n];
        __nv_bfloat16 h = __float2bfloat16_rn(v);
        u_hi[i] = h;
        u_lo[i] = __float2bfloat16_rn(v - __bfloat162float(h));
    }
}
__global__ void conv_v_k(const float* __restrict__ V) {
    size_t i = (size_t)blockIdx.x * blockDim.x + threadIdx.x;
    if (i < (size_t)G4 * HIDn) {
        size_t n = i / HIDn, k = i % HIDn;
        float v = V[k * G4 + n];
        __half h = __float2half_rn(v);
        vt_h[i] = h;
        vt_l[i] = __float2half_rn(v - __half2float(h));
    }
}

// ---------------------------------------------------------------------------
// Phase 1: bf16-split HMMA GEMM (unchanged from R4 — known good).
// ---------------------------------------------------------------------------
#define SA   80
#define T1B  (128 * SA)
#define BUFB (4 * T1B)
#define SM1  (2 * BUFB)

#define P1_LOADREG(kc) do { \
    _Pragma("unroll") \
    for (int i = 0; i < 8; ++i) { \
        int e = tid + i * 256; int tl = e >> 9; int rr = (e >> 2) & 127; int c4 = e & 3; \
        const __nv_bfloat16* bp = (tl == 0) ? x_hi : (tl == 1) ? x_lo : (tl == 2) ? u_hi : u_lo; \
        int r0 = ((tl < 2) ? m0 : n0) + rr; \
        pf[i] = *(const float4*)(bp + (size_t)r0 * INn + (kc) * 32 + c4 * 8); \
    } } while (0)
#define P1_STORE(b) do { \
    _Pragma("unroll") \
    for (int i = 0; i < 8; ++i) { \
        int e = tid + i * 256; int tl = e >> 9; int rr = (e >> 2) & 127; int c4 = e & 3; \
        *(float4*)(sm + (b) * BUFB + tl * T1B + rr * SA + c4 * 16) = pf[i]; \
    } } while (0)

__global__ __launch_bounds__(256, 1) void gemm_xu_mma(const float* __restrict__ bias) {
    extern __shared__ char sm[];
    const uint32_t smb = smem_u32(sm);
    const int tid = threadIdx.x, w = tid >> 5, l = tid & 31;
    const int m0 = blockIdx.y * 128, n0 = blockIdx.x * 128;
    const int wm = w >> 1, wn = w & 1;
    const int gr = l >> 2, q = l & 3;
    const int rA = (l & 7) + ((l >> 3) & 1) * 8, cA = (l >> 4) * 16;
    const int rB = (l & 7) + ((l >> 4) & 1) * 8, cB = ((l >> 3) & 1) * 16;

    float acc[2][8][4];
#pragma unroll
    for (int a = 0; a < 2; ++a)
#pragma unroll
        for (int b = 0; b < 8; ++b)
#pragma unroll
            for (int c = 0; c < 4; ++c) acc[a][b][c] = 0.0f;

    float4 pf[8];
    P1_LOADREG(0);
    P1_STORE(0);
    P1_LOADREG(1);
    __syncthreads();

    for (int kc = 0; kc < 32; ++kc) {
        const int buf = kc & 1;
        if (kc + 1 < 32) P1_STORE(buf ^ 1);
        if (kc + 2 < 32) P1_LOADREG(kc + 2);

        const uint32_t base = smb + buf * BUFB;
#pragma unroll
        for (int ks = 0; ks < 2; ++ks) {
            uint32_t ah[2][4], al[2][4];
#pragma unroll
            for (int mfi = 0; mfi < 2; ++mfi) {
                uint32_t ra = base + (uint32_t)((wm * 32 + mfi * 16 + rA) * SA + ks * 32 + cA);
                ldsm4(ah[mfi], ra);
                ldsm4(al[mfi], ra + T1B);
            }
#pragma unroll
            for (int np = 0; np < 4; ++np) {
                uint32_t rb = base + 2 * T1B +
                              (uint32_t)((wn * 64 + np * 16 + rB) * SA + ks * 32 + cB);
                uint32_t bh[4], bl[4];
                ldsm4(bh, rb);
                ldsm4(bl, rb + T1B);
#pragma unroll
                for (int mfi = 0; mfi < 2; ++mfi) {
                    mma_bf16(acc[mfi][2 * np],     ah[mfi], bh[0], bh[1]);
                    mma_bf16(acc[mfi][2 * np + 1], ah[mfi], bh[2], bh[3]);
                    mma_bf16(acc[mfi][2 * np],     al[mfi], bh[0], bh[1]);
                    mma_bf16(acc[mfi][2 * np + 1], al[mfi], bh[2], bh[3]);
                    mma_bf16(acc[mfi][2 * np],     ah[mfi], bl[0], bl[1]);
                    mma_bf16(acc[mfi][2 * np + 1], ah[mfi], bl[2], bl[3]);
                }
            }
        }
        __syncthreads();
    }

#pragma unroll
    for (int mfi = 0; mfi < 2; ++mfi) {
#pragma unroll
        for (int nf = 0; nf < 8; ++nf) {
            int row = m0 + wm * 32 + mfi * 16 + gr;
            int col = n0 + wn * 64 + nf * 8 + 2 * q;
            float2 bz = *(const float2*)(bias + col);
            float2 w0 = make_float2(acc[mfi][nf][0] + bz.x, acc[mfi][nf][1] + bz.y);
            float2 w1 = make_float2(acc[mfi][nf][2] + bz.x, acc[mfi][nf][3] + bz.y);
            *(float2*)(g_scr + (size_t)row * G4 + col) = w0;
            *(float2*)(g_scr + (size_t)(row + 8) * G4 + col) = w1;
        }
    }
}

// ---------------------------------------------------------------------------
// Phase 2: persistent fp16 HMMA recurrence. V^T fp16 hi/lo resident in SMEM;
// h as single fp16 plane; CG-style release/acquire grid barrier.
// ---------------------------------------------------------------------------
#define KP     2064                       // VT smem row stride bytes
#define VT_LO  66048                      // 32*KP
#define HA     132096                     // A buffers start
#define HTB2   17408                      // 64*272, single fp16 plane
#define GSM_O  (HA + 2 * HTB2)            // 166912
#define SM2    (GSM_O + 64 * 33 * 4)      // 175360

#define P2_LOADREG(ch) do { \
    _Pragma("unroll") \
    for (int i = 0; i < 4; ++i) { \
        int e = tid + i * 256; int rr = e >> 4; int c16 = e & 15; \
        pf[i] = *(const float4*)(hh + (size_t)rr * HIDn + (ch) * 128 + c16 * 8); \
    } } while (0)
#define P2_STORE(b) do { \
    _Pragma("unroll") \
    for (int i = 0; i < 4; ++i) { \
        int e = tid + i * 256; int rr = e >> 4; int c16 = e & 15; \
        *(float4*)(sm + HA + (b) * HTB2 + rr * 272 + c16 * 16) = pf[i]; \
    } } while (0)

__global__ __launch_bounds__(NTHR, 1) void lstm_persist_mma(float* __restrict__ out) {
    extern __shared__ char sm[];
    const uint32_t smb = smem_u32(sm);
    float* gsm = (float*)(sm + GSM_O);
    const int tid = threadIdx.x, w = tid >> 5, l = tid & 31;
    const int j0 = blockIdx.x * 8;
    const int mf = w >> 1, nb = (w & 1) * 16;
    const int gr = l >> 2, q = l & 3;
    const int rA = (l & 7) + ((l >> 3) & 1) * 8, cA = (l >> 4) * 16;
    const int rB = (l & 7) + ((l >> 4) & 1) * 8, cB = ((l >> 3) & 1) * 16;

    // Load V^T slice (32 gate-cols x 1024 k, fp16 hi+lo) once: 8192 float4.
#pragma unroll
    for (int i = 0; i < 32; ++i) {
        int e = tid + i * 256;
        int pl = e >> 12, r = (e >> 7) & 31, c = e & 127;
        int gv = (r >> 3) * 1024 + j0 + (r & 7);
        const __half* src = pl ? vt_l : vt_h;
        *(float4*)(sm + pl * VT_LO + r * KP + c * 16) =
            *(const float4*)(src + (size_t)gv * HIDn + c * 8);
    }
    __syncthreads();

    for (int t = 0; t < Sn; ++t) {
        const __half* hh = hb[t & 1];

        // Prefetch this step's x@U+bias values into registers.
        float2 gpre[4];
        {
            int m = mf * 16 + gr;
            const float* gp = g_scr + ((size_t)(m * Sn + t)) * G4;
#pragma unroll
            for (int nf = 0; nf < 2; ++nf) {
                int c = nb + nf * 8 + 2 * q;
                int gcol = (c >> 3) * HIDn + j0 + (c & 7);
                gpre[nf * 2]     = *(const float2*)(gp + gcol);
                gpre[nf * 2 + 1] = *(const float2*)(gp + (size_t)8 * Sn * G4 + gcol);
            }
        }

        float acc[2][4];
#pragma unroll
        for (int a = 0; a < 2; ++a)
#pragma unroll
            for (int c = 0; c < 4; ++c) acc[a][c] = 0.0f;

        float4 pf[4];
        P2_LOADREG(0);
        P2_STORE(0);
        P2_LOADREG(1);
        __syncthreads();

        for (int ch = 0; ch < 8; ++ch) {
            const int buf = ch & 1;
            if (ch + 1 < 8) P2_STORE(buf ^ 1);
            if (ch + 2 < 8) P2_LOADREG(ch + 2);

            const uint32_t ab = smb + HA + buf * HTB2 + (uint32_t)((mf * 16 + rA) * 272 + cA);
            const uint32_t bb = smb + (uint32_t)((nb + rB) * KP + ch * 256 + cB);
#pragma unroll
            for (int ks = 0; ks < 8; ++ks) {
                uint32_t a4[4], bh4[4], bl4[4];
                ldsm4(a4, ab + ks * 32);
                ldsm4(bh4, bb + ks * 32);
                ldsm4(bl4, bb + ks * 32 + VT_LO);
                mma_f16(acc[0], a4, bh4[0], bh4[1]);
                mma_f16(acc[1], a4, bh4[2], bh4[3]);
                mma_f16(acc[0], a4, bl4[0], bl4[1]);
                mma_f16(acc[1], a4, bl4[2], bl4[3]);
            }
            __syncthreads();
        }

        // Stage pre-activations into gsm.
#pragma unroll
        for (int nf = 0; nf < 2; ++nf) {
            int m = mf * 16 + gr;
            int c = nb + nf * 8 + 2 * q;
            gsm[m * 33 + c]           = acc[nf][0] + gpre[nf * 2].x;
            gsm[m * 33 + c + 1]       = acc[nf][1] + gpre[nf * 2].y;
            gsm[(m + 8) * 33 + c]     = acc[nf][2] + gpre[nf * 2 + 1].x;
            gsm[(m + 8) * 33 + c + 1] = acc[nf][3] + gpre[nf * 2 + 1].y;
        }
        __syncthreads();

        // Gates.
        const int nxt = (t & 1) ^ 1;
#pragma unroll
        for (int p = 0; p < 2; ++p) {
            int e  = tid + p * 256;
            int m  = e >> 3;
            int jj = e & 7;
            float gn = gsm[m * 33 + jj];
            float gi = gsm[m * 33 + 8 + jj];
            float gf = gsm[m * 33 + 16 + jj];
            float go = gsm[m * 33 + 24 + jj];
            float nv = tanh_f(gn);
            float iv = sigmoid_f(gi);
            float fv = sigmoid_f(gf);
            float ov = sigmoid_f(go);
            int idx = m * HIDn + j0 + jj;
            float cn = c_buf[idx] * fv + nv * iv;
            c_buf[idx] = cn;
            float hn = tanh_f(cn) * ov;
            out[((size_t)m * Sn + t) * HIDn + j0 + jj] = hn;
            hb[nxt][idx] = __float2half_rn(hn);
            if (t == Sn - 1) h_fin[idx] = hn;
        }

        // ---- grid-wide barrier (CG pattern: red.release + ld.acquire) ----
        __syncthreads();
        if (tid == 0) {
            unsigned int* gc = &g_count;
            asm volatile("red.release.gpu.global.add.u32 [%0], %1;"
                         :: "l"(gc), "r"(1u) : "memory");
            unsigned target = (unsigned)(t + 1) * NCTA;
            unsigned v;
            int spins = 0;
            for (;;) {
                asm volatile("ld.acquire.gpu.global.u32 %0, [%1];"
                             : "=r"(v) : "l"(gc) : "memory");
                if (v >= target) break;
                if (++spins > 32) { __nanosleep(64); spins = 0; }
            }
        }
        __syncthreads();
    }
}

__global__ void finalize_k(float* __restrict__ out_tail) {
    int i = blockIdx.x * blockDim.x + threadIdx.x;
    if (i < Bn * HIDn) {
        out_tail[i]             = h_fin[i];
        out_tail[Bn * HIDn + i] = c_buf[i];
    }
}

extern "C" void kernel_launch(void* const* d_in, const int* in_sizes, int n_in,
                              void* d_out, int out_size) {
    const float* x    = (const float*)d_in[0];
    const float* U    = (const float*)d_in[1];
    const float* V    = (const float*)d_in[2];
    const float* bias = (const float*)d_in[3];
    const float* h0   = (const float*)d_in[4];
    const float* c0   = (const float*)d_in[5];
    float* out = (float*)d_out;

    static int attr_done = 0;
    if (!attr_done) {
        cudaFuncSetAttribute(gemm_xu_mma,
                             cudaFuncAttributeMaxDynamicSharedMemorySize, SM1);
        cudaFuncSetAttribute(lstm_persist_mma,
                             cudaFuncAttributeMaxDynamicSharedMemorySize, SM2);
        attr_done = 1;
    }

    init_state_k<<<(Bn * HIDn + 255) / 256, 256>>>(h0, c0);
    conv_x_k<<<(int)(((size_t)Mtot * INn + 255) / 256), 256>>>(x);
    conv_u_k<<<(int)(((size_t)G4 * INn + 255) / 256), 256>>>(U);
    conv_v_k<<<(int)(((size_t)G4 * HIDn + 255) / 256), 256>>>(V);

    dim3 gg(G4 / 128, Mtot / 128);
    gemm_xu_mma<<<gg, 256, SM1>>>(bias);

    lstm_persist_mma<<<NCTA, NTHR, SM2>>>(out);

    long long main_elems = (long long)Bn * Sn * HIDn;
    if ((long long)out_size >= main_elems + 2LL * Bn * HIDn) {
        finalize_k<<<(Bn * HIDn + 255) / 256, 256>>>(out + main_elems);
    }
}

// round 6
// speedup vs baseline: 4.3075x; 1.0553x over previous
#include <cuda_runtime.h>
#include <cuda_bf16.h>
#include <cuda_fp16.h>
#include <stdint.h>

#define Bn   64
#define Sn   512
#define INn  1024
#define HIDn 1024
#define G4   4096
#define Mtot 32768
#define NCTA 128
#define NTHR 256

// ---- device scratch ----
__device__ float g_scr[(size_t)Mtot * G4];              // x@U + bias (512MB)
__device__ float c_buf[Bn * HIDn];
__device__ float h_fin[Bn * HIDn];
__device__ int   g_flags[Sn + 1][4];                    // per-step h-chunk ready counters
__device__ __nv_bfloat16 x_hi[(size_t)Mtot * INn];
__device__ __nv_bfloat16 x_lo[(size_t)Mtot * INn];
__device__ __nv_bfloat16 u_hi[(size_t)G4 * INn];        // U^T [N][K]
__device__ __nv_bfloat16 u_lo[(size_t)G4 * INn];
__device__ __half vt_h[(size_t)G4 * HIDn];              // V^T [N][K] fp16
__device__ __half hb[2][Bn * HIDn];                     // h carried as fp16

// ---- helpers ----
__device__ __forceinline__ uint32_t smem_u32(const void* p) {
    uint32_t a;
    asm("{ .reg .u64 t; cvta.to.shared.u64 t, %1; cvt.u32.u64 %0, t; }" : "=r"(a) : "l"(p));
    return a;
}
__device__ __forceinline__ void ldsm4(uint32_t r[4], uint32_t addr) {
    asm volatile("ldmatrix.sync.aligned.m8n8.x4.shared.b16 {%0,%1,%2,%3}, [%4];"
        : "=r"(r[0]), "=r"(r[1]), "=r"(r[2]), "=r"(r[3]) : "r"(addr));
}
__device__ __forceinline__ void mma_bf16(float c[4], const uint32_t a[4],
                                         uint32_t b0, uint32_t b1) {
    asm volatile("mma.sync.aligned.m16n8k16.row.col.f32.bf16.bf16.f32 "
        "{%0,%1,%2,%3}, {%4,%5,%6,%7}, {%8,%9}, {%0,%1,%2,%3};"
        : "+f"(c[0]), "+f"(c[1]), "+f"(c[2]), "+f"(c[3])
        : "r"(a[0]), "r"(a[1]), "r"(a[2]), "r"(a[3]), "r"(b0), "r"(b1));
}
__device__ __forceinline__ void mma_f16(float c[4], const uint32_t a[4],
                                        uint32_t b0, uint32_t b1) {
    asm volatile("mma.sync.aligned.m16n8k16.row.col.f32.f16.f16.f32 "
        "{%0,%1,%2,%3}, {%4,%5,%6,%7}, {%8,%9}, {%0,%1,%2,%3};"
        : "+f"(c[0]), "+f"(c[1]), "+f"(c[2]), "+f"(c[3])
        : "r"(a[0]), "r"(a[1]), "r"(a[2]), "r"(a[3]), "r"(b0), "r"(b1));
}
__device__ __forceinline__ float sigmoid_f(float x) { return 1.0f / (1.0f + __expf(-x)); }
__device__ __forceinline__ float tanh_f(float x) { return 2.0f / (1.0f + __expf(-2.0f * x)) - 1.0f; }

// ---------------------------------------------------------------------------
__global__ void init_state_k(const float* __restrict__ h0,
                             const float* __restrict__ c0) {
    int i = blockIdx.x * blockDim.x + threadIdx.x;
    if (i < Bn * HIDn) {
        c_buf[i] = c0[i];
        hb[0][i] = __float2half_rn(h0[i]);
        h_fin[i] = h0[i];
    }
    if (i < (Sn + 1) * 4) ((int*)g_flags)[i] = (i < 4) ? 32 : 0;
}

__global__ void conv_x_k(const float* __restrict__ x) {
    size_t i = (size_t)blockIdx.x * blockDim.x + threadIdx.x;
    if (i < (size_t)Mtot * INn) {
        float v = x[i];
        __nv_bfloat16 h = __float2bfloat16_rn(v);
        x_hi[i] = h;
        x_lo[i] = __float2bfloat16_rn(v - __bfloat162float(h));
    }
}
__global__ void conv_u_k(const float* __restrict__ U) {
    size_t i = (size_t)blockIdx.x * blockDim.x + threadIdx.x;
    if (i < (size_t)G4 * INn) {
        size_t n = i / INn, k = i % INn;
        float v = U[k * G4 + n];
        __nv_bfloat16 h = __float2bfloat16_rn(v);
        u_hi[i] = h;
        u_lo[i] = __float2bfloat16_rn(v - __bfloat162float(h));
    }
}
__global__ void conv_v_k(const float* __restrict__ V) {
    size_t i = (size_t)blockIdx.x * blockDim.x + threadIdx.x;
    if (i < (size_t)G4 * HIDn) {
        size_t n = i / HIDn, k = i % HIDn;
        vt_h[i] = __float2half_rn(V[k * G4 + n]);
    }
}

// ---------------------------------------------------------------------------
// Phase 1: bf16-split HMMA GEMM (unchanged — known good).
// ---------------------------------------------------------------------------
#define SA   80
#define T1B  (128 * SA)
#define BUFB (4 * T1B)
#define SM1  (2 * BUFB)

#define P1_LOADREG(kc) do { \
    _Pragma("unroll") \
    for (int i = 0; i < 8; ++i) { \
        int e = tid + i * 256; int tl = e >> 9; int rr = (e >> 2) & 127; int c4 = e & 3; \
        const __nv_bfloat16* bp = (tl == 0) ? x_hi : (tl == 1) ? x_lo : (tl == 2) ? u_hi : u_lo; \
        int r0 = ((tl < 2) ? m0 : n0) + rr; \
        pf[i] = *(const float4*)(bp + (size_t)r0 * INn + (kc) * 32 + c4 * 8); \
    } } while (0)
#define P1_STORE(b) do { \
    _Pragma("unroll") \
    for (int i = 0; i < 8; ++i) { \
        int e = tid + i * 256; int tl = e >> 9; int rr = (e >> 2) & 127; int c4 = e & 3; \
        *(float4*)(sm + (b) * BUFB + tl * T1B + rr * SA + c4 * 16) = pf[i]; \
    } } while (0)

__global__ __launch_bounds__(256, 1) void gemm_xu_mma(const float* __restrict__ bias) {
    extern __shared__ char sm[];
    const uint32_t smb = smem_u32(sm);
    const int tid = threadIdx.x, w = tid >> 5, l = tid & 31;
    const int m0 = blockIdx.y * 128, n0 = blockIdx.x * 128;
    const int wm = w >> 1, wn = w & 1;
    const int gr = l >> 2, q = l & 3;
    const int rA = (l & 7) + ((l >> 3) & 1) * 8, cA = (l >> 4) * 16;
    const int rB = (l & 7) + ((l >> 4) & 1) * 8, cB = ((l >> 3) & 1) * 16;

    float acc[2][8][4];
#pragma unroll
    for (int a = 0; a < 2; ++a)
#pragma unroll
        for (int b = 0; b < 8; ++b)
#pragma unroll
            for (int c = 0; c < 4; ++c) acc[a][b][c] = 0.0f;

    float4 pf[8];
    P1_LOADREG(0);
    P1_STORE(0);
    P1_LOADREG(1);
    __syncthreads();

    for (int kc = 0; kc < 32; ++kc) {
        const int buf = kc & 1;
        if (kc + 1 < 32) P1_STORE(buf ^ 1);
        if (kc + 2 < 32) P1_LOADREG(kc + 2);

        const uint32_t base = smb + buf * BUFB;
#pragma unroll
        for (int ks = 0; ks < 2; ++ks) {
            uint32_t ah[2][4], al[2][4];
#pragma unroll
            for (int mfi = 0; mfi < 2; ++mfi) {
                uint32_t ra = base + (uint32_t)((wm * 32 + mfi * 16 + rA) * SA + ks * 32 + cA);
                ldsm4(ah[mfi], ra);
                ldsm4(al[mfi], ra + T1B);
            }
#pragma unroll
            for (int np = 0; np < 4; ++np) {
                uint32_t rb = base + 2 * T1B +
                              (uint32_t)((wn * 64 + np * 16 + rB) * SA + ks * 32 + cB);
                uint32_t bh[4], bl[4];
                ldsm4(bh, rb);
                ldsm4(bl, rb + T1B);
#pragma unroll
                for (int mfi = 0; mfi < 2; ++mfi) {
                    mma_bf16(acc[mfi][2 * np],     ah[mfi], bh[0], bh[1]);
                    mma_bf16(acc[mfi][2 * np + 1], ah[mfi], bh[2], bh[3]);
                    mma_bf16(acc[mfi][2 * np],     al[mfi], bh[0], bh[1]);
                    mma_bf16(acc[mfi][2 * np + 1], al[mfi], bh[2], bh[3]);
                    mma_bf16(acc[mfi][2 * np],     ah[mfi], bl[0], bl[1]);
                    mma_bf16(acc[mfi][2 * np + 1], ah[mfi], bl[2], bl[3]);
                }
            }
        }
        __syncthreads();
    }

#pragma unroll
    for (int mfi = 0; mfi < 2; ++mfi) {
#pragma unroll
        for (int nf = 0; nf < 8; ++nf) {
            int row = m0 + wm * 32 + mfi * 16 + gr;
            int col = n0 + wn * 64 + nf * 8 + 2 * q;
            float2 bz = *(const float2*)(bias + col);
            float2 w0 = make_float2(acc[mfi][nf][0] + bz.x, acc[mfi][nf][1] + bz.y);
            float2 w1 = make_float2(acc[mfi][nf][2] + bz.x, acc[mfi][nf][3] + bz.y);
            *(float2*)(g_scr + (size_t)row * G4 + col) = w0;
            *(float2*)(g_scr + (size_t)(row + 8) * G4 + col) = w1;
        }
    }
}

// ---------------------------------------------------------------------------
// Phase 2: persistent recurrence, de-serialized.
//  - single fp16 V plane resident in SMEM (64KB)
//  - whole h (4 chunks x 256 kcols) cp.async'd into 4 dedicated smem buffers
//  - per-chunk producer flags (release/acquire) replace the global barrier
// ---------------------------------------------------------------------------
#define KP     2064                       // VT smem row stride bytes
#define HB_OFF 66048                      // 32*KP
#define HROW   528                        // 256 fp16 + 16B pad
#define HBUFB  (64 * HROW)                // 33792
#define GSM_O  (HB_OFF + 4 * HBUFB)       // 201216
#define SM2    (GSM_O + 64 * 33 * 4)      // 209664

#define POLL_FLAG(pt, pc) do { \
    const int* _fp = &g_flags[(pt)][(pc)]; \
    int _v, _sp = 0; \
    for (;;) { \
        asm volatile("ld.acquire.gpu.global.s32 %0, [%1];" : "=r"(_v) : "l"(_fp) : "memory"); \
        if (_v >= 32) break; \
        if (++_sp > 16) { __nanosleep(64); _sp = 0; } \
    } } while (0)

#define P2_ISSUE(ch) do { \
    _Pragma("unroll") \
    for (int i = 0; i < 8; ++i) { \
        int e = tid + i * 256; int rr = e >> 5; int c16 = e & 31; \
        uint32_t dst = smb + HB_OFF + (ch) * HBUFB + rr * HROW + c16 * 16; \
        const __half* src = hh + (size_t)rr * HIDn + (ch) * 256 + c16 * 8; \
        asm volatile("cp.async.ca.shared.global [%0], [%1], 16;" :: "r"(dst), "l"(src) : "memory"); \
    } \
    asm volatile("cp.async.commit_group;" ::: "memory"); } while (0)

#define P2_COMPUTE(ch) do { \
    const uint32_t ab = smb + HB_OFF + (ch) * HBUFB + (uint32_t)((mf * 16 + rA) * HROW + cA); \
    const uint32_t bb = smb + (uint32_t)((nb + rB) * KP + (ch) * 512 + cB); \
    _Pragma("unroll") \
    for (int ks = 0; ks < 16; ++ks) { \
        uint32_t a4[4], b4[4]; \
        ldsm4(a4, ab + ks * 32); \
        ldsm4(b4, bb + ks * 32); \
        mma_f16(acc[0], a4, b4[0], b4[1]); \
        mma_f16(acc[1], a4, b4[2], b4[3]); \
    } } while (0)

__global__ __launch_bounds__(NTHR, 1) void lstm_persist_mma(float* __restrict__ out) {
    extern __shared__ char sm[];
    const uint32_t smb = smem_u32(sm);
    float* gsm = (float*)(sm + GSM_O);
    const int tid = threadIdx.x, w = tid >> 5, l = tid & 31;
    const int j0 = blockIdx.x * 8;
    const int mf = w >> 1, nb = (w & 1) * 16;
    const int gr = l >> 2, q = l & 3;
    const int rA = (l & 7) + ((l >> 3) & 1) * 8, cA = (l >> 4) * 16;
    const int rB = (l & 7) + ((l >> 4) & 1) * 8, cB = ((l >> 3) & 1) * 16;
    const int my_chunk = blockIdx.x >> 5;    // which h-chunk this CTA produces

    // Load V^T slice (32 gate-cols x 1024 k, fp16) once: 64KB.
#pragma unroll
    for (int i = 0; i < 16; ++i) {
        int e = tid + i * 256;
        int r = e >> 7, c = e & 127;
        int gv = (r >> 3) * 1024 + j0 + (r & 7);
        *(float4*)(sm + r * KP + c * 16) = *(const float4*)(vt_h + (size_t)gv * HIDn + c * 8);
    }
    __syncthreads();

    for (int t = 0; t < Sn; ++t) {
        const __half* hh = hb[t & 1];

        // Prefetch this step's x@U+bias values into registers (DRAM, deep latency).
        float2 gpre[4];
        {
            int m = mf * 16 + gr;
            const float* gp = g_scr + ((size_t)(m * Sn + t)) * G4;
#pragma unroll
            for (int nf = 0; nf < 2; ++nf) {
                int c = nb + nf * 8 + 2 * q;
                int gcol = (c >> 3) * HIDn + j0 + (c & 7);
                gpre[nf * 2]     = *(const float2*)(gp + gcol);
                gpre[nf * 2 + 1] = *(const float2*)(gp + (size_t)8 * Sn * G4 + gcol);
            }
        }

        float acc[2][4];
#pragma unroll
        for (int a = 0; a < 2; ++a)
#pragma unroll
            for (int c = 0; c < 4; ++c) acc[a][c] = 0.0f;

        POLL_FLAG(t, 0);
        P2_ISSUE(0);
        POLL_FLAG(t, 1);
        P2_ISSUE(1);

        // ch = 0
        asm volatile("cp.async.wait_group 1;" ::: "memory");
        __syncthreads();
        P2_COMPUTE(0);
        POLL_FLAG(t, 2);
        P2_ISSUE(2);
        // ch = 1
        asm volatile("cp.async.wait_group 1;" ::: "memory");
        __syncthreads();
        P2_COMPUTE(1);
        POLL_FLAG(t, 3);
        P2_ISSUE(3);
        // ch = 2
        asm volatile("cp.async.wait_group 1;" ::: "memory");
        __syncthreads();
        P2_COMPUTE(2);
        // ch = 3
        asm volatile("cp.async.wait_group 0;" ::: "memory");
        __syncthreads();
        P2_COMPUTE(3);

        // Stage pre-activations into gsm.
#pragma unroll
        for (int nf = 0; nf < 2; ++nf) {
            int m = mf * 16 + gr;
            int c = nb + nf * 8 + 2 * q;
            gsm[m * 33 + c]           = acc[nf][0] + gpre[nf * 2].x;
            gsm[m * 33 + c + 1]       = acc[nf][1] + gpre[nf * 2].y;
            gsm[(m + 8) * 33 + c]     = acc[nf][2] + gpre[nf * 2 + 1].x;
            gsm[(m + 8) * 33 + c + 1] = acc[nf][3] + gpre[nf * 2 + 1].y;
        }
        __syncthreads();

        // Gates.
        const int nxt = (t & 1) ^ 1;
#pragma unroll
        for (int p = 0; p < 2; ++p) {
            int e  = tid + p * 256;
            int m  = e >> 3;
            int jj = e & 7;
            float gn = gsm[m * 33 + jj];
            float gi = gsm[m * 33 + 8 + jj];
            float gf = gsm[m * 33 + 16 + jj];
            float go = gsm[m * 33 + 24 + jj];
            float nv = tanh_f(gn);
            float iv = sigmoid_f(gi);
            float fv = sigmoid_f(gf);
            float ov = sigmoid_f(go);
            int idx = m * HIDn + j0 + jj;
            float cn = c_buf[idx] * fv + nv * iv;
            c_buf[idx] = cn;
            float hn = tanh_f(cn) * ov;
            out[((size_t)m * Sn + t) * HIDn + j0 + jj] = hn;
            hb[nxt][idx] = __float2half_rn(hn);
            if (t == Sn - 1) h_fin[idx] = hn;
        }

        // Publish: this CTA's h columns for step t+1 are ready.
        __syncthreads();
        if (tid == 0) {
            const int* fp = &g_flags[t + 1][my_chunk];
            asm volatile("red.release.gpu.global.add.s32 [%0], %1;"
                         :: "l"(fp), "r"(1) : "memory");
        }
    }
}

__global__ void finalize_k(float* __restrict__ out_tail) {
    int i = blockIdx.x * blockDim.x + threadIdx.x;
    if (i < Bn * HIDn) {
        out_tail[i]             = h_fin[i];
        out_tail[Bn * HIDn + i] = c_buf[i];
    }
}

extern "C" void kernel_launch(void* const* d_in, const int* in_sizes, int n_in,
                              void* d_out, int out_size) {
    const float* x    = (const float*)d_in[0];
    const float* U    = (const float*)d_in[1];
    const float* V    = (const float*)d_in[2];
    const float* bias = (const float*)d_in[3];
    const float* h0   = (const float*)d_in[4];
    const float* c0   = (const float*)d_in[5];
    float* out = (float*)d_out;

    static int attr_done = 0;
    if (!attr_done) {
        cudaFuncSetAttribute(gemm_xu_mma,
                             cudaFuncAttributeMaxDynamicSharedMemorySize, SM1);
        cudaFuncSetAttribute(lstm_persist_mma,
                             cudaFuncAttributeMaxDynamicSharedMemorySize, SM2);
        attr_done = 1;
    }

    init_state_k<<<(Bn * HIDn + 255) / 256, 256>>>(h0, c0);
    conv_x_k<<<(int)(((size_t)Mtot * INn + 255) / 256), 256>>>(x);
    conv_u_k<<<(int)(((size_t)G4 * INn + 255) / 256), 256>>>(U);
    conv_v_k<<<(int)(((size_t)G4 * HIDn + 255) / 256), 256>>>(V);

    dim3 gg(G4 / 128, Mtot / 128);
    gemm_xu_mma<<<gg, 256, SM1>>>(bias);

    lstm_persist_mma<<<NCTA, NTHR, SM2>>>(out);

    long long main_elems = (long long)Bn * Sn * HIDn;
    if ((long long)out_size >= main_elems + 2LL * Bn * HIDn) {
        finalize_k<<<(Bn * HIDn + 255) / 256, 256>>>(out + main_elems);
    }
}